// round 12
// baseline (speedup 1.0000x reference)
#include <cuda_runtime.h>
#include <cstdint>

#define BATCH 4096
#define DIM   768
#define NEXP  16
#define KD    1536
#define KSEL  50
#define NPAIR (BATCH*2)

// ---------------- f32x2 packed-math macros ----------------
#define FMA2(d,a,b) asm("fma.rn.f32x2 %0, %1, %2, %3;" : "=l"(d) : "l"(a), "l"(b), "l"(d))
#define PACK2(d,lo,hi) asm("mov.b64 %0, {%1, %2};" : "=l"(d) : "f"(lo), "f"(hi))
#define UNPACK2(lo,hi,v) asm("mov.b64 {%0, %1}, %2;" : "=f"(lo), "=f"(hi) : "l"(v))
typedef unsigned long long u64;

// ---------------- device scratch ----------------
__device__ float g_F[NPAIR * KD];       // masked relu activations, 50.3 MB
__device__ float g_w[NPAIR];            // gate weight per (token,slot)
__device__ int   g_route[NPAIR];        // expert id per (token,slot)
__device__ int   g_cnt[NEXP];
__device__ int   g_list[NEXP * BATCH];

// ---------------- init ----------------
__global__ void k_init() {
    if (threadIdx.x < NEXP) g_cnt[threadIdx.x] = 0;
}

// ---------------- gate + route: one warp per token ----------------
__global__ void __launch_bounds__(128) k_gate(const float* __restrict__ x,
                                              const float* __restrict__ Wg,
                                              const float* __restrict__ bg,
                                              const float* __restrict__ b_gate) {
    int b = blockIdx.x * 4 + (threadIdx.x >> 5);
    int lane = threadIdx.x & 31;
    const float* xr = x + (size_t)b * DIM;

    float pe[NEXP];
#pragma unroll
    for (int e = 0; e < NEXP; e++) pe[e] = 0.f;
    for (int d = lane; d < DIM; d += 32) {
        float xv = xr[d] - b_gate[d];
#pragma unroll
        for (int e = 0; e < NEXP; e++) pe[e] += xv * Wg[e * DIM + d];
    }
#pragma unroll
    for (int e = 0; e < NEXP; e++) {
#pragma unroll
        for (int o = 16; o > 0; o >>= 1) pe[e] += __shfl_xor_sync(0xffffffffu, pe[e], o);
        pe[e] += bg[e];
    }
    float m = pe[0];
#pragma unroll
    for (int e = 1; e < NEXP; e++) m = fmaxf(m, pe[e]);
    float s = 0.f;
#pragma unroll
    for (int e = 0; e < NEXP; e++) { pe[e] = expf(pe[e] - m); s += pe[e]; }
    float inv = 1.f / s;
    float v1 = -1.f, v2 = -1.f; int i1 = 0, i2 = 0;
#pragma unroll
    for (int e = 0; e < NEXP; e++) {
        float p = pe[e] * inv;
        if (p > v1)      { v2 = v1; i2 = i1; v1 = p; i1 = e; }
        else if (p > v2) { v2 = p;  i2 = e; }
    }
    float e1 = expf(v1), e2 = expf(v2);
    float w0 = e1 / (e1 + e2), w1 = e2 / (e1 + e2);

    if (lane == 0) {
        int p0 = b * 2, p1 = b * 2 + 1;
        g_route[p0] = i1; g_route[p1] = i2;
        g_w[p0] = w0;     g_w[p1] = w1;
        int q0 = atomicAdd(&g_cnt[i1], 1); g_list[i1 * BATCH + q0] = p0;
        int q1 = atomicAdd(&g_cnt[i2], 1); g_list[i2 * BATCH + q1] = p1;
    }
}

// ---------------- grouped encode GEMM: K-packed f32x2, no PACK in hot loop ----------------
// tile 128(M) x 64(N), K-chunks of 16, 256 threads, microtile 8M x 4N x 4K
// smem layout: row-major [row][k], rows padded to 20 floats (80 B) for bank spread
#define TM 128
#define TN 64
#define TK 16
#define ROWP 20   // padded row stride in floats (80 B, 16B-aligned)

struct __align__(16) SmemEnc {
    float Xs[2][TM * ROWP];
    float Ws[2][TN * ROWP];
    int   pair[TM];
    float bias[TN];
};

__global__ void __launch_bounds__(256, 2) k_encode(const float* __restrict__ x,
                                                   const float* __restrict__ b_dec,
                                                   const float* __restrict__ Wenc,
                                                   const float* __restrict__ benc) {
    __shared__ SmemEnc sm;
    int e  = blockIdx.y >> 5;
    int mt = blockIdx.y & 31;
    int cnt = g_cnt[e];
    int m0 = mt * TM;
    if (m0 >= cnt) return;
    int n0 = blockIdx.x * TN;

    int tid = threadIdx.x;
    if (tid < TM) {
        int m = m0 + tid;
        sm.pair[tid] = (m < cnt) ? g_list[e * BATCH + m] : -1;
    }
    if (tid < TN) sm.bias[tid] = benc[(size_t)e * KD + n0 + tid];
    __syncthreads();

    int tx = tid & 15, ty = tid >> 4;

    u64 acc[8][4];
#pragma unroll
    for (int i = 0; i < 8; i++)
#pragma unroll
        for (int j = 0; j < 4; j++) acc[i][j] = 0ULL;

    // X loader: thread -> row mx = tid>>1 (0..127), k-offset hx = (tid&1)*8, two float4
    int mx = tid >> 1;
    int hx = (tid & 1) * 8;
    int pairL = sm.pair[mx];
    int tokenL = (pairL >= 0 ? pairL : 0) >> 1;
    const float* xrow = x + (size_t)tokenL * DIM + hx;
    const float* brow = b_dec + hx;
    // W loader: thread -> row nw = tid>>2 (0..63), k-offset hw = (tid&3)*4, one float4
    int nw = tid >> 2;
    int hw = (tid & 3) * 4;
    const float* wrow = Wenc + ((size_t)e * KD + n0 + nw) * DIM + hw;

    // prologue: chunk 0 into buf 0
    {
        float4 xa = *(const float4*)(xrow);
        float4 xb = *(const float4*)(xrow + 4);
        float4 ba = *(const float4*)(brow);
        float4 bb = *(const float4*)(brow + 4);
        xa.x -= ba.x; xa.y -= ba.y; xa.z -= ba.z; xa.w -= ba.w;
        xb.x -= bb.x; xb.y -= bb.y; xb.z -= bb.z; xb.w -= bb.w;
        *(float4*)&sm.Xs[0][mx * ROWP + hx]     = xa;
        *(float4*)&sm.Xs[0][mx * ROWP + hx + 4] = xb;
        float4 wa = *(const float4*)(wrow);
        *(float4*)&sm.Ws[0][nw * ROWP + hw] = wa;
    }
    __syncthreads();

    int buf = 0;
#pragma unroll 1
    for (int c = 1; c <= DIM / TK; c++) {
        float4 xa, xb, wa;
        if (c < DIM / TK) {
            xa = *(const float4*)(xrow + c * TK);
            xb = *(const float4*)(xrow + c * TK + 4);
            float4 ba = *(const float4*)(brow + c * TK);
            float4 bb = *(const float4*)(brow + c * TK + 4);
            xa.x -= ba.x; xa.y -= ba.y; xa.z -= ba.z; xa.w -= ba.w;
            xb.x -= bb.x; xb.y -= bb.y; xb.z -= bb.z; xb.w -= bb.w;
            wa = *(const float4*)(wrow + c * TK);
        }
        // compute on buf
#pragma unroll
        for (int q = 0; q < TK / 4; q++) {
            int kc = q * 4;
            // B: 4 rows (n = tx + 16j), natural (k,k+1)/(k+2,k+3) u64 pairs
            ulonglong2 B01[4];
#pragma unroll
            for (int j = 0; j < 4; j++)
                B01[j] = *(const ulonglong2*)&sm.Ws[buf][(tx + 16 * j) * ROWP + kc];
#pragma unroll
            for (int i = 0; i < 8; i++) {
                ulonglong2 A = *(const ulonglong2*)&sm.Xs[buf][(ty + 16 * i) * ROWP + kc];
#pragma unroll
                for (int j = 0; j < 4; j++) FMA2(acc[i][j], A.x, B01[j].x);
#pragma unroll
                for (int j = 0; j < 4; j++) FMA2(acc[i][j], A.y, B01[j].y);
            }
        }
        if (c < DIM / TK) {
            int nb = buf ^ 1;
            *(float4*)&sm.Xs[nb][mx * ROWP + hx]     = xa;
            *(float4*)&sm.Xs[nb][mx * ROWP + hx + 4] = xb;
            *(float4*)&sm.Ws[nb][nw * ROWP + hw]     = wa;
            __syncthreads();
            buf = nb;
        }
    }

    // epilogue: fold (even,odd) partials, bias + relu + gate-weight
#pragma unroll
    for (int i = 0; i < 8; i++) {
        int m = ty + 16 * i;
        int pair = sm.pair[m];
        if (pair < 0) continue;
        float w = g_w[pair];
        float* dst = g_F + (size_t)pair * KD + n0;
#pragma unroll
        for (int j = 0; j < 4; j++) {
            int n = tx + 16 * j;
            float lo, hi;
            UNPACK2(lo, hi, acc[i][j]);
            dst[n] = fmaxf(lo + hi + sm.bias[n], 0.f) * w;
        }
    }
}

// ---------------- decode: hist + 1-barrier-per-iter radix top-50 ----------------
__global__ void __launch_bounds__(192) k_decode(const float* __restrict__ b_dec,
                                                const float* __restrict__ Wdec,
                                                float* __restrict__ out) {
    int b = blockIdx.x;
    int tid = threadIdx.x;
    int lane = tid & 31;
    int wid = tid >> 5;

    __shared__ float    sf[KD];
    __shared__ int      hist[256];
    __shared__ int      cntS[23];
    __shared__ int      sel[56];
    __shared__ int      s_nsel, s_E, s_special;

    float4 bd = *(const float4*)(b_dec + tid * 4);
    u64 acc01, acc23;
    PACK2(acc01, bd.x, bd.y);
    PACK2(acc23, bd.z, bd.w);

    for (int slot = 0; slot < 2; slot++) {
        int pair = b * 2 + slot;
        int e = g_route[pair];
        const float* Fr = g_F + (size_t)pair * KD;

        for (int i = tid; i < 256; i += 192) hist[i] = 0;
        if (tid < 23) cntS[tid] = 0;
        unsigned rv[8];
#pragma unroll
        for (int j = 0; j < 8; j++) {
            float v = Fr[tid + 192 * j];
            sf[tid + 192 * j] = v;
            rv[j] = __float_as_uint(v);
        }
        __syncthreads();

#pragma unroll
        for (int j = 0; j < 8; j++)
            if (rv[j]) atomicAdd(&hist[rv[j] >> 23], 1);
        __syncthreads();

        if (wid == 0) {
            int base = 255 - 8 * lane;
            int c[8], cl = 0;
#pragma unroll
            for (int j = 0; j < 8; j++) { c[j] = hist[base - j]; cl += c[j]; }
            int incl = cl;
#pragma unroll
            for (int o = 1; o < 32; o <<= 1) {
                int t = __shfl_up_sync(0xffffffffu, incl, o);
                if (lane >= o) incl += t;
            }
            int pre = incl - cl;
            int total = __shfl_sync(0xffffffffu, incl, 31);
            if (total < KSEL) {
                if (lane == 0) s_special = 1;
            } else {
                bool owns = (pre < KSEL) && (incl >= KSEL);
                unsigned om = __ballot_sync(0xffffffffu, owns);
                int ol = __ffs(om) - 1;
                int Ev = 0;
                if (owns) {
                    int cum = pre;
#pragma unroll
                    for (int j = 0; j < 8; j++) {
                        if (cum + c[j] >= KSEL) { Ev = base - j; break; }
                        cum += c[j];
                    }
                }
                Ev = __shfl_sync(0xffffffffu, Ev, ol);
                if (lane == 0) { s_special = 0; s_E = Ev; }
            }
        }
        __syncthreads();

        unsigned thr;
        if (!s_special) {
            unsigned lo = (unsigned)s_E << 23;
#pragma unroll 1
            for (int it = 0; it < 23; it++) {
                int bit = 22 - it;
                unsigned t = lo | (1u << bit);
                int c = 0;
#pragma unroll
                for (int j = 0; j < 8; j++) c += (rv[j] >= t);
                c = __reduce_add_sync(0xffffffffu, c);
                if (lane == 0) atomicAdd(&cntS[it], c);
                __syncthreads();
                if (cntS[it] >= KSEL) lo |= (1u << bit);
            }
            thr = lo;
        } else {
            thr = 1u;
        }

        if (tid < 32) {
            int ns = 0;
            for (int base = 0; base < KD; base += 32) {
                unsigned bits = __float_as_uint(sf[base + tid]);
                bool p = (bits >= thr) && (bits != 0u);
                unsigned msk = __ballot_sync(0xffffffffu, p);
                int pos = ns + __popc(msk & ((1u << tid) - 1u));
                if (p && pos < KSEL) sel[pos] = base + tid;
                ns += __popc(msk);
            }
            if (tid == 0) s_nsel = (ns < KSEL ? ns : KSEL);
        }
        __syncthreads();
        int nsel = s_nsel;

        const float* Wd = Wdec + (size_t)e * KD * DIM + tid * 4;
        int i = 0;
        for (; i + 4 <= nsel; i += 4) {
            int k0 = sel[i], k1 = sel[i + 1], k2 = sel[i + 2], k3 = sel[i + 3];
            float f0 = sf[k0], f1 = sf[k1], f2 = sf[k2], f3 = sf[k3];
            float4 w0 = *(const float4*)(Wd + (size_t)k0 * DIM);
            float4 w1 = *(const float4*)(Wd + (size_t)k1 * DIM);
            float4 w2 = *(const float4*)(Wd + (size_t)k2 * DIM);
            float4 w3 = *(const float4*)(Wd + (size_t)k3 * DIM);
            u64 fp, t;
            PACK2(fp, f0, f0);
            PACK2(t, w0.x, w0.y); FMA2(acc01, fp, t);
            PACK2(t, w0.z, w0.w); FMA2(acc23, fp, t);
            PACK2(fp, f1, f1);
            PACK2(t, w1.x, w1.y); FMA2(acc01, fp, t);
            PACK2(t, w1.z, w1.w); FMA2(acc23, fp, t);
            PACK2(fp, f2, f2);
            PACK2(t, w2.x, w2.y); FMA2(acc01, fp, t);
            PACK2(t, w2.z, w2.w); FMA2(acc23, fp, t);
            PACK2(fp, f3, f3);
            PACK2(t, w3.x, w3.y); FMA2(acc01, fp, t);
            PACK2(t, w3.z, w3.w); FMA2(acc23, fp, t);
        }
        for (; i < nsel; i++) {
            int k0 = sel[i];
            float f0 = sf[k0];
            float4 w0 = *(const float4*)(Wd + (size_t)k0 * DIM);
            u64 fp, t;
            PACK2(fp, f0, f0);
            PACK2(t, w0.x, w0.y); FMA2(acc01, fp, t);
            PACK2(t, w0.z, w0.w); FMA2(acc23, fp, t);
        }
        __syncthreads();
    }

    float4 r;
    UNPACK2(r.x, r.y, acc01);
    UNPACK2(r.z, r.w, acc23);
    *(float4*)(out + (size_t)b * DIM + tid * 4) = r;
}

// ---------------- launch ----------------
extern "C" void kernel_launch(void* const* d_in, const int* in_sizes, int n_in,
                              void* d_out, int out_size) {
    const float* x      = (const float*)d_in[0];
    const float* Wg     = (const float*)d_in[1];
    const float* bg     = (const float*)d_in[2];
    const float* b_gate = (const float*)d_in[3];
    const float* b_dec  = (const float*)d_in[4];
    const float* Wenc   = (const float*)d_in[5];
    const float* benc   = (const float*)d_in[6];
    const float* Wdec   = (const float*)d_in[7];
    float* out = (float*)d_out;

    k_init<<<1, 32>>>();
    k_gate<<<BATCH / 4, 128>>>(x, Wg, bg, b_gate);
    k_encode<<<dim3(KD / TN, NEXP * 32), 256>>>(x, b_dec, Wenc, benc);
    k_decode<<<BATCH, 192>>>(b_dec, Wdec, out);
}

// round 13
// speedup vs baseline: 1.1141x; 1.1141x over previous
#include <cuda_runtime.h>
#include <cstdint>

#define BATCH 4096
#define DIM   768
#define NEXP  16
#define KD    1536
#define KSEL  50
#define NPAIR (BATCH*2)

// ---------------- f32x2 packed-math macros ----------------
#define FMA2(d,a,b) asm("fma.rn.f32x2 %0, %1, %2, %3;" : "=l"(d) : "l"(a), "l"(b), "l"(d))
#define PACK2(d,lo,hi) asm("mov.b64 %0, {%1, %2};" : "=l"(d) : "f"(lo), "f"(hi))
#define UNPACK2(lo,hi,v) asm("mov.b64 {%0, %1}, %2;" : "=f"(lo), "=f"(hi) : "l"(v))
typedef unsigned long long u64;

// ---------------- device scratch ----------------
__device__ float g_F[NPAIR * KD];       // masked relu activations, 50.3 MB
__device__ float g_w[NPAIR];            // gate weight per (token,slot)
__device__ int   g_route[NPAIR];        // expert id per (token,slot)
__device__ int   g_cnt[NEXP];
__device__ int   g_list[NEXP * BATCH];
__device__ int   g_work;                // persistent-encode work counter
__device__ int   g_ntiles;              // number of (expert, mt) tiles
__device__ int   g_tile_e[NEXP * 32];
__device__ int   g_tile_mt[NEXP * 32];

// ---------------- init ----------------
__global__ void k_init() {
    if (threadIdx.x < NEXP) g_cnt[threadIdx.x] = 0;
}

// ---------------- gate + route: one warp per token ----------------
__global__ void __launch_bounds__(128) k_gate(const float* __restrict__ x,
                                              const float* __restrict__ Wg,
                                              const float* __restrict__ bg,
                                              const float* __restrict__ b_gate) {
    int b = blockIdx.x * 4 + (threadIdx.x >> 5);
    int lane = threadIdx.x & 31;
    const float* xr = x + (size_t)b * DIM;

    float pe[NEXP];
#pragma unroll
    for (int e = 0; e < NEXP; e++) pe[e] = 0.f;
    for (int d = lane; d < DIM; d += 32) {
        float xv = xr[d] - b_gate[d];
#pragma unroll
        for (int e = 0; e < NEXP; e++) pe[e] += xv * Wg[e * DIM + d];
    }
#pragma unroll
    for (int e = 0; e < NEXP; e++) {
#pragma unroll
        for (int o = 16; o > 0; o >>= 1) pe[e] += __shfl_xor_sync(0xffffffffu, pe[e], o);
        pe[e] += bg[e];
    }
    float m = pe[0];
#pragma unroll
    for (int e = 1; e < NEXP; e++) m = fmaxf(m, pe[e]);
    float s = 0.f;
#pragma unroll
    for (int e = 0; e < NEXP; e++) { pe[e] = expf(pe[e] - m); s += pe[e]; }
    float inv = 1.f / s;
    float v1 = -1.f, v2 = -1.f; int i1 = 0, i2 = 0;
#pragma unroll
    for (int e = 0; e < NEXP; e++) {
        float p = pe[e] * inv;
        if (p > v1)      { v2 = v1; i2 = i1; v1 = p; i1 = e; }
        else if (p > v2) { v2 = p;  i2 = e; }
    }
    float e1 = expf(v1), e2 = expf(v2);
    float w0 = e1 / (e1 + e2), w1 = e2 / (e1 + e2);

    if (lane == 0) {
        int p0 = b * 2, p1 = b * 2 + 1;
        g_route[p0] = i1; g_route[p1] = i2;
        g_w[p0] = w0;     g_w[p1] = w1;
        int q0 = atomicAdd(&g_cnt[i1], 1); g_list[i1 * BATCH + q0] = p0;
        int q1 = atomicAdd(&g_cnt[i2], 1); g_list[i2 * BATCH + q1] = p1;
    }
}

// ---------------- build tile table (after gate) ----------------
__global__ void k_prep() {
    if (threadIdx.x == 0) {
        int t = 0;
        for (int e = 0; e < NEXP; e++) {
            int nt = (g_cnt[e] + 127) >> 7;
            for (int m = 0; m < nt; m++) { g_tile_e[t] = e; g_tile_mt[t] = m; t++; }
        }
        g_ntiles = t;
        g_work = 0;
    }
}

// ---------------- grouped encode GEMM (R8 body, persistent scheduling) ----------------
// tile 128(M pairs) x 128(N dict), K-chunks of 16, 256 threads, 8x8 microtile
#define TM 128
#define TN 128
#define TK 16
#define LDP 132   // padded row stride (floats)
#define NBLK (KD / TN)   // 12 n-blocks per tile

struct __align__(16) SmemEnc {
    float Xs[2][TK][LDP];
    float Ws[2][TK][LDP];
    int   pair[TM];
};

__global__ void __launch_bounds__(256, 2) k_encode(const float* __restrict__ x,
                                                   const float* __restrict__ b_dec,
                                                   const float* __restrict__ Wenc,
                                                   const float* __restrict__ benc) {
    __shared__ SmemEnc sm;
    __shared__ int s_w;

    int tid = threadIdx.x;
    int tx = tid & 15, ty = tid >> 4;
    int lr  = tid >> 1;            // loader row 0..127
    int kc0 = (tid & 1) * 8;       // loader k-offset 0 or 8
    int tot = g_ntiles * NBLK;

#pragma unroll 1
    while (true) {
        if (tid == 0) s_w = atomicAdd(&g_work, 1);
        __syncthreads();
        int w = s_w;
        if (w >= tot) break;
        int tile = w / NBLK;
        int nb   = w - tile * NBLK;
        int e  = g_tile_e[tile];
        int mt = g_tile_mt[tile];
        int cnt = g_cnt[e];
        int m0 = mt * TM;
        int n0 = nb * TN;

        if (tid < TM) {
            int m = m0 + tid;
            sm.pair[tid] = (m < cnt) ? g_list[e * BATCH + m] : -1;
        }
        __syncthreads();

        u64 acc[8][4];
#pragma unroll
        for (int i = 0; i < 8; i++)
#pragma unroll
            for (int j = 0; j < 4; j++) acc[i][j] = 0ULL;

        int pairL = sm.pair[lr];
        int tokenL = (pairL >= 0 ? pairL : 0) >> 1;
        const float* xrow = x + (size_t)tokenL * DIM + kc0;
        const float* wrow = Wenc + (size_t)e * KD * DIM + (size_t)(n0 + lr) * DIM + kc0;
        const float* brow = b_dec + kc0;

        float4 nxA = *(const float4*)(xrow);
        float4 nxB = *(const float4*)(xrow + 4);
        float4 nbA = *(const float4*)(brow);
        float4 nbB = *(const float4*)(brow + 4);
        float4 nwA = *(const float4*)(wrow);
        float4 nwB = *(const float4*)(wrow + 4);
        nxA.x -= nbA.x; nxA.y -= nbA.y; nxA.z -= nbA.z; nxA.w -= nbA.w;
        nxB.x -= nbB.x; nxB.y -= nbB.y; nxB.z -= nbB.z; nxB.w -= nbB.w;
        sm.Xs[0][kc0 + 0][lr] = nxA.x; sm.Xs[0][kc0 + 1][lr] = nxA.y;
        sm.Xs[0][kc0 + 2][lr] = nxA.z; sm.Xs[0][kc0 + 3][lr] = nxA.w;
        sm.Xs[0][kc0 + 4][lr] = nxB.x; sm.Xs[0][kc0 + 5][lr] = nxB.y;
        sm.Xs[0][kc0 + 6][lr] = nxB.z; sm.Xs[0][kc0 + 7][lr] = nxB.w;
        sm.Ws[0][kc0 + 0][lr] = nwA.x; sm.Ws[0][kc0 + 1][lr] = nwA.y;
        sm.Ws[0][kc0 + 2][lr] = nwA.z; sm.Ws[0][kc0 + 3][lr] = nwA.w;
        sm.Ws[0][kc0 + 4][lr] = nwB.x; sm.Ws[0][kc0 + 5][lr] = nwB.y;
        sm.Ws[0][kc0 + 6][lr] = nwB.z; sm.Ws[0][kc0 + 7][lr] = nwB.w;
        __syncthreads();

        int buf = 0;
#pragma unroll 1
        for (int c = 1; c < DIM / TK; c++) {
            nxA = *(const float4*)(xrow + c * TK);
            nxB = *(const float4*)(xrow + c * TK + 4);
            nbA = *(const float4*)(brow + c * TK);
            nbB = *(const float4*)(brow + c * TK + 4);
            nwA = *(const float4*)(wrow + c * TK);
            nwB = *(const float4*)(wrow + c * TK + 4);
            nxA.x -= nbA.x; nxA.y -= nbA.y; nxA.z -= nbA.z; nxA.w -= nbA.w;
            nxB.x -= nbB.x; nxB.y -= nbB.y; nxB.z -= nbB.z; nxB.w -= nbB.w;
#pragma unroll
            for (int kk = 0; kk < TK; kk++) {
                float4 a0 = *(const float4*)&sm.Xs[buf][kk][ty * 8];
                float4 a1 = *(const float4*)&sm.Xs[buf][kk][ty * 8 + 4];
                ulonglong2 b0 = *(const ulonglong2*)&sm.Ws[buf][kk][tx * 8];
                ulonglong2 b1 = *(const ulonglong2*)&sm.Ws[buf][kk][tx * 8 + 4];
                float av[8] = {a0.x, a0.y, a0.z, a0.w, a1.x, a1.y, a1.z, a1.w};
#pragma unroll
                for (int i = 0; i < 8; i++) {
                    u64 ad; PACK2(ad, av[i], av[i]);
                    FMA2(acc[i][0], ad, b0.x);
                    FMA2(acc[i][1], ad, b0.y);
                    FMA2(acc[i][2], ad, b1.x);
                    FMA2(acc[i][3], ad, b1.y);
                }
            }
            int nbuf = buf ^ 1;
            sm.Xs[nbuf][kc0 + 0][lr] = nxA.x; sm.Xs[nbuf][kc0 + 1][lr] = nxA.y;
            sm.Xs[nbuf][kc0 + 2][lr] = nxA.z; sm.Xs[nbuf][kc0 + 3][lr] = nxA.w;
            sm.Xs[nbuf][kc0 + 4][lr] = nxB.x; sm.Xs[nbuf][kc0 + 5][lr] = nxB.y;
            sm.Xs[nbuf][kc0 + 6][lr] = nxB.z; sm.Xs[nbuf][kc0 + 7][lr] = nxB.w;
            sm.Ws[nbuf][kc0 + 0][lr] = nwA.x; sm.Ws[nbuf][kc0 + 1][lr] = nwA.y;
            sm.Ws[nbuf][kc0 + 2][lr] = nwA.z; sm.Ws[nbuf][kc0 + 3][lr] = nwA.w;
            sm.Ws[nbuf][kc0 + 4][lr] = nwB.x; sm.Ws[nbuf][kc0 + 5][lr] = nwB.y;
            sm.Ws[nbuf][kc0 + 6][lr] = nwB.z; sm.Ws[nbuf][kc0 + 7][lr] = nwB.w;
            __syncthreads();
            buf = nbuf;
        }
        // last chunk
#pragma unroll
        for (int kk = 0; kk < TK; kk++) {
            float4 a0 = *(const float4*)&sm.Xs[buf][kk][ty * 8];
            float4 a1 = *(const float4*)&sm.Xs[buf][kk][ty * 8 + 4];
            ulonglong2 b0 = *(const ulonglong2*)&sm.Ws[buf][kk][tx * 8];
            ulonglong2 b1 = *(const ulonglong2*)&sm.Ws[buf][kk][tx * 8 + 4];
            float av[8] = {a0.x, a0.y, a0.z, a0.w, a1.x, a1.y, a1.z, a1.w};
#pragma unroll
            for (int i = 0; i < 8; i++) {
                u64 ad; PACK2(ad, av[i], av[i]);
                FMA2(acc[i][0], ad, b0.x);
                FMA2(acc[i][1], ad, b0.y);
                FMA2(acc[i][2], ad, b1.x);
                FMA2(acc[i][3], ad, b1.y);
            }
        }

        // epilogue: bias + relu + gate-weight, store to g_F
        const float* be = benc + (size_t)e * KD + n0 + tx * 8;
        float4 bl = *(const float4*)(be);
        float4 bh = *(const float4*)(be + 4);
#pragma unroll
        for (int i = 0; i < 8; i++) {
            int m = ty * 8 + i;
            int pair = sm.pair[m];
            if (pair < 0) continue;
            float w = g_w[pair];
            float c0, c1, c2, c3, c4, c5, c6, c7;
            UNPACK2(c0, c1, acc[i][0]);
            UNPACK2(c2, c3, acc[i][1]);
            UNPACK2(c4, c5, acc[i][2]);
            UNPACK2(c6, c7, acc[i][3]);
            float4 r0, r1;
            r0.x = fmaxf(c0 + bl.x, 0.f) * w; r0.y = fmaxf(c1 + bl.y, 0.f) * w;
            r0.z = fmaxf(c2 + bl.z, 0.f) * w; r0.w = fmaxf(c3 + bl.w, 0.f) * w;
            r1.x = fmaxf(c4 + bh.x, 0.f) * w; r1.y = fmaxf(c5 + bh.y, 0.f) * w;
            r1.z = fmaxf(c6 + bh.z, 0.f) * w; r1.w = fmaxf(c7 + bh.w, 0.f) * w;
            float* dst = g_F + (size_t)pair * KD + n0 + tx * 8;
            *(float4*)(dst)     = r0;
            *(float4*)(dst + 4) = r1;
        }
        __syncthreads();   // epilogue reads of sm.pair done before next tile writes
    }
}

// ---------------- decode: hist + 2-bit radix top-50 ----------------
__global__ void __launch_bounds__(192) k_decode(const float* __restrict__ b_dec,
                                                const float* __restrict__ Wdec,
                                                float* __restrict__ out) {
    int b = blockIdx.x;
    int tid = threadIdx.x;
    int lane = tid & 31;
    int wid = tid >> 5;

    __shared__ float    sf[KD];
    __shared__ int      hist[256];
    __shared__ int      cntS[36];
    __shared__ int      sel[56];
    __shared__ int      s_nsel, s_E, s_special;

    float4 bd = *(const float4*)(b_dec + tid * 4);
    u64 acc01, acc23;
    PACK2(acc01, bd.x, bd.y);
    PACK2(acc23, bd.z, bd.w);

    for (int slot = 0; slot < 2; slot++) {
        int pair = b * 2 + slot;
        int e = g_route[pair];
        const float* Fr = g_F + (size_t)pair * KD;

        for (int i = tid; i < 256; i += 192) hist[i] = 0;
        if (tid < 36) cntS[tid] = 0;
        unsigned rv[8];
#pragma unroll
        for (int j = 0; j < 8; j++) {
            float v = Fr[tid + 192 * j];
            sf[tid + 192 * j] = v;
            rv[j] = __float_as_uint(v);
        }
        __syncthreads();

        // exponent histogram (nonzero only; f >= 0)
#pragma unroll
        for (int j = 0; j < 8; j++)
            if (rv[j]) atomicAdd(&hist[rv[j] >> 23], 1);
        __syncthreads();

        // warp 0: find boundary exponent bin E (or special: < KSEL nonzero)
        if (wid == 0) {
            int base = 255 - 8 * lane;
            int c[8], cl = 0;
#pragma unroll
            for (int j = 0; j < 8; j++) { c[j] = hist[base - j]; cl += c[j]; }
            int incl = cl;
#pragma unroll
            for (int o = 1; o < 32; o <<= 1) {
                int t = __shfl_up_sync(0xffffffffu, incl, o);
                if (lane >= o) incl += t;
            }
            int pre = incl - cl;
            int total = __shfl_sync(0xffffffffu, incl, 31);
            if (total < KSEL) {
                if (lane == 0) s_special = 1;
            } else {
                bool owns = (pre < KSEL) && (incl >= KSEL);
                unsigned om = __ballot_sync(0xffffffffu, owns);
                int ol = __ffs(om) - 1;
                int Ev = 0;
                if (owns) {
                    int cum = pre;
#pragma unroll
                    for (int j = 0; j < 8; j++) {
                        if (cum + c[j] >= KSEL) { Ev = base - j; break; }
                        cum += c[j];
                    }
                }
                Ev = __shfl_sync(0xffffffffu, Ev, ol);
                if (lane == 0) { s_special = 0; s_E = Ev; }
            }
        }
        __syncthreads();

        unsigned thr;
        if (!s_special) {
            unsigned lo = (unsigned)s_E << 23;
            // 11 x 2-bit groups over mantissa bits 22..1
#pragma unroll 1
            for (int it = 0; it < 11; it++) {
                int s = 21 - 2 * it;
                unsigned t1 = lo | (1u << s);
                unsigned t2 = lo | (2u << s);
                unsigned t3 = lo | (3u << s);
                int c1 = 0, c2 = 0, c3 = 0;
#pragma unroll
                for (int j = 0; j < 8; j++) {
                    c1 += (rv[j] >= t1);
                    c2 += (rv[j] >= t2);
                    c3 += (rv[j] >= t3);
                }
                c1 = __reduce_add_sync(0xffffffffu, c1);
                c2 = __reduce_add_sync(0xffffffffu, c2);
                c3 = __reduce_add_sync(0xffffffffu, c3);
                if (lane == 0) {
                    atomicAdd(&cntS[it * 3 + 0], c1);
                    atomicAdd(&cntS[it * 3 + 1], c2);
                    atomicAdd(&cntS[it * 3 + 2], c3);
                }
                __syncthreads();
                int C1 = cntS[it * 3 + 0], C2 = cntS[it * 3 + 1], C3 = cntS[it * 3 + 2];
                unsigned d = (C3 >= KSEL) ? 3u : (C2 >= KSEL) ? 2u : (C1 >= KSEL) ? 1u : 0u;
                lo |= d << s;
            }
            // final bit 0
            {
                unsigned t = lo | 1u;
                int c = 0;
#pragma unroll
                for (int j = 0; j < 8; j++) c += (rv[j] >= t);
                c = __reduce_add_sync(0xffffffffu, c);
                if (lane == 0) atomicAdd(&cntS[33], c);
                __syncthreads();
                if (cntS[33] >= KSEL) lo |= 1u;
            }
            thr = lo;
        } else {
            thr = 1u;
        }

        // order-preserving compaction by warp 0 (exclude exact zeros, cap KSEL)
        if (tid < 32) {
            int ns = 0;
            for (int base = 0; base < KD; base += 32) {
                unsigned bits = __float_as_uint(sf[base + tid]);
                bool p = (bits >= thr) && (bits != 0u);
                unsigned msk = __ballot_sync(0xffffffffu, p);
                int pos = ns + __popc(msk & ((1u << tid) - 1u));
                if (p && pos < KSEL) sel[pos] = base + tid;
                ns += __popc(msk);
            }
            if (tid == 0) s_nsel = (ns < KSEL ? ns : KSEL);
        }
        __syncthreads();
        int nsel = s_nsel;

        // gather-accumulate, 4-row unroll for MLP
        const float* Wd = Wdec + (size_t)e * KD * DIM + tid * 4;
        int i = 0;
        for (; i + 4 <= nsel; i += 4) {
            int k0 = sel[i], k1 = sel[i + 1], k2 = sel[i + 2], k3 = sel[i + 3];
            float f0 = sf[k0], f1 = sf[k1], f2 = sf[k2], f3 = sf[k3];
            float4 w0 = *(const float4*)(Wd + (size_t)k0 * DIM);
            float4 w1 = *(const float4*)(Wd + (size_t)k1 * DIM);
            float4 w2 = *(const float4*)(Wd + (size_t)k2 * DIM);
            float4 w3 = *(const float4*)(Wd + (size_t)k3 * DIM);
            u64 fp, t;
            PACK2(fp, f0, f0);
            PACK2(t, w0.x, w0.y); FMA2(acc01, fp, t);
            PACK2(t, w0.z, w0.w); FMA2(acc23, fp, t);
            PACK2(fp, f1, f1);
            PACK2(t, w1.x, w1.y); FMA2(acc01, fp, t);
            PACK2(t, w1.z, w1.w); FMA2(acc23, fp, t);
            PACK2(fp, f2, f2);
            PACK2(t, w2.x, w2.y); FMA2(acc01, fp, t);
            PACK2(t, w2.z, w2.w); FMA2(acc23, fp, t);
            PACK2(fp, f3, f3);
            PACK2(t, w3.x, w3.y); FMA2(acc01, fp, t);
            PACK2(t, w3.z, w3.w); FMA2(acc23, fp, t);
        }
        for (; i < nsel; i++) {
            int k0 = sel[i];
            float f0 = sf[k0];
            float4 w0 = *(const float4*)(Wd + (size_t)k0 * DIM);
            u64 fp, t;
            PACK2(fp, f0, f0);
            PACK2(t, w0.x, w0.y); FMA2(acc01, fp, t);
            PACK2(t, w0.z, w0.w); FMA2(acc23, fp, t);
        }
        __syncthreads();
    }

    float4 r;
    UNPACK2(r.x, r.y, acc01);
    UNPACK2(r.z, r.w, acc23);
    *(float4*)(out + (size_t)b * DIM + tid * 4) = r;
}

// ---------------- launch ----------------
extern "C" void kernel_launch(void* const* d_in, const int* in_sizes, int n_in,
                              void* d_out, int out_size) {
    const float* x      = (const float*)d_in[0];
    const float* Wg     = (const float*)d_in[1];
    const float* bg     = (const float*)d_in[2];
    const float* b_gate = (const float*)d_in[3];
    const float* b_dec  = (const float*)d_in[4];
    const float* Wenc   = (const float*)d_in[5];
    const float* benc   = (const float*)d_in[6];
    const float* Wdec   = (const float*)d_in[7];
    float* out = (float*)d_out;

    k_init<<<1, 32>>>();
    k_gate<<<BATCH / 4, 128>>>(x, Wg, bg, b_gate);
    k_prep<<<1, 32>>>();
    k_encode<<<296, 256>>>(x, b_dec, Wenc, benc);
    k_decode<<<BATCH, 192>>>(b_dec, Wdec, out);
}

// round 14
// speedup vs baseline: 1.3405x; 1.2032x over previous
#include <cuda_runtime.h>
#include <cstdint>

#define BATCH 4096
#define DIM   768
#define NEXP  16
#define KD    1536
#define KSEL  50
#define NPAIR (BATCH*2)

// ---------------- f32x2 packed-math macros (decode) ----------------
#define FMA2(d,a,b) asm("fma.rn.f32x2 %0, %1, %2, %3;" : "=l"(d) : "l"(a), "l"(b), "l"(d))
#define PACK2(d,lo,hi) asm("mov.b64 %0, {%1, %2};" : "=l"(d) : "f"(lo), "f"(hi))
#define UNPACK2(lo,hi,v) asm("mov.b64 {%0, %1}, %2;" : "=f"(lo), "=f"(hi) : "l"(v))
typedef unsigned long long u64;

// ---------------- device scratch ----------------
__device__ float g_X[BATCH * DIM];      // x - b_dec, 12.6 MB
__device__ float g_F[NPAIR * KD];       // masked relu activations, 50.3 MB
__device__ float g_w[NPAIR];
__device__ int   g_route[NPAIR];
__device__ int   g_cnt[NEXP];
__device__ int   g_list[NEXP * BATCH];
__device__ int   g_work;
__device__ int   g_done;
__device__ int   g_ntiles;
__device__ int   g_tile_e[NEXP * 32];
__device__ int   g_tile_mt[NEXP * 32];

// ---------------- tf32 helpers ----------------
__device__ __forceinline__ uint32_t f2tf(float v) {
    uint32_t r; asm("cvt.rna.tf32.f32 %0, %1;" : "=r"(r) : "f"(v)); return r;
}
// m16n8k8 tf32 MMA: D(4f) += A(4 b32) * B(2 b32)
__device__ __forceinline__ void mma_tf32(float* c, const uint32_t* a, const uint32_t* b) {
    asm("mma.sync.aligned.m16n8k8.row.col.f32.tf32.tf32.f32 "
        "{%0,%1,%2,%3}, {%4,%5,%6,%7}, {%8,%9}, {%0,%1,%2,%3};"
        : "+f"(c[0]), "+f"(c[1]), "+f"(c[2]), "+f"(c[3])
        : "r"(a[0]), "r"(a[1]), "r"(a[2]), "r"(a[3]), "r"(b[0]), "r"(b[1]));
}

// ---------------- init ----------------
__global__ void k_init() {
    if (threadIdx.x < NEXP) g_cnt[threadIdx.x] = 0;
    if (threadIdx.x == NEXP) g_done = 0;
}

// ---------------- gate + route + x-prep; last block builds tile table ----------------
__global__ void __launch_bounds__(128) k_gate(const float* __restrict__ x,
                                              const float* __restrict__ Wg,
                                              const float* __restrict__ bg,
                                              const float* __restrict__ b_gate,
                                              const float* __restrict__ b_dec) {
    int b = blockIdx.x * 4 + (threadIdx.x >> 5);
    int lane = threadIdx.x & 31;
    const float* xr = x + (size_t)b * DIM;

    float pe[NEXP];
#pragma unroll
    for (int e = 0; e < NEXP; e++) pe[e] = 0.f;
    for (int d = lane; d < DIM; d += 32) {
        float xv = xr[d];
        g_X[(size_t)b * DIM + d] = xv - b_dec[d];
        xv -= b_gate[d];
#pragma unroll
        for (int e = 0; e < NEXP; e++) pe[e] += xv * Wg[e * DIM + d];
    }
#pragma unroll
    for (int e = 0; e < NEXP; e++) {
#pragma unroll
        for (int o = 16; o > 0; o >>= 1) pe[e] += __shfl_xor_sync(0xffffffffu, pe[e], o);
        pe[e] += bg[e];
    }
    float m = pe[0];
#pragma unroll
    for (int e = 1; e < NEXP; e++) m = fmaxf(m, pe[e]);
    float s = 0.f;
#pragma unroll
    for (int e = 0; e < NEXP; e++) { pe[e] = expf(pe[e] - m); s += pe[e]; }
    float inv = 1.f / s;
    float v1 = -1.f, v2 = -1.f; int i1 = 0, i2 = 0;
#pragma unroll
    for (int e = 0; e < NEXP; e++) {
        float p = pe[e] * inv;
        if (p > v1)      { v2 = v1; i2 = i1; v1 = p; i1 = e; }
        else if (p > v2) { v2 = p;  i2 = e; }
    }
    float e1 = expf(v1), e2 = expf(v2);
    float w0 = e1 / (e1 + e2), w1 = e2 / (e1 + e2);

    if (lane == 0) {
        int p0 = b * 2, p1 = b * 2 + 1;
        g_route[p0] = i1; g_route[p1] = i2;
        g_w[p0] = w0;     g_w[p1] = w1;
        int q0 = atomicAdd(&g_cnt[i1], 1); g_list[i1 * BATCH + q0] = p0;
        int q1 = atomicAdd(&g_cnt[i2], 1); g_list[i2 * BATCH + q1] = p1;
    }
    // last finished block builds the encode tile table
    __syncthreads();
    if (threadIdx.x == 0) {
        __threadfence();
        int old = atomicAdd(&g_done, 1);
        if (old == gridDim.x - 1) {
            int t = 0;
            for (int e = 0; e < NEXP; e++) {
                int nt = (g_cnt[e] + 127) >> 7;
                for (int mm = 0; mm < nt; mm++) { g_tile_e[t] = e; g_tile_mt[t] = mm; t++; }
            }
            g_ntiles = t;
            g_work = 0;
            g_done = 0;
        }
    }
}

// ---------------- encode: tf32 mma.sync GEMM (3x split), persistent ----------------
// block tile 128M x 128N, K-chunks CK=16 double-buffered, 8 warps (4M x 2N grid)
// warp tile 32M x 64N = 2 m-tiles(16) x 8 n-tiles(8) of m16n8k8
#define CK   16
#define NCH  (DIM / CK)      // 48
#define SROW 20              // smem row stride (floats): conflict-free frag LDS
#define NBLK (KD / 128)      // 12 n-blocks per tile

__global__ void __launch_bounds__(256, 2) k_encode(const float* __restrict__ Wenc,
                                                   const float* __restrict__ benc) {
    __shared__ float Xs[2][128 * SROW];
    __shared__ float Ws[2][128 * SROW];
    __shared__ int   s_pair[128];
    __shared__ float s_bias[128];
    __shared__ int   s_w;

    int tid  = threadIdx.x;
    int wid  = tid >> 5;
    int lane = tid & 31;
    int g = lane >> 2, t = lane & 3;
    int warp_m = wid & 3;        // 0..3
    int warp_n = wid >> 2;       // 0..1
    int mbase = warp_m * 32;
    int nbase = warp_n * 64;
    int lrow = tid >> 1;         // loader row 0..127
    int lh   = (tid & 1) * 8;    // loader k-offset 0 or 8
    int tot = g_ntiles * NBLK;

#pragma unroll 1
    while (true) {
        if (tid == 0) s_w = atomicAdd(&g_work, 1);
        __syncthreads();
        int w = s_w;
        if (w >= tot) break;
        int tile = w / NBLK;
        int nb   = w - tile * NBLK;
        int e  = g_tile_e[tile];
        int mt = g_tile_mt[tile];
        int cnt = g_cnt[e];
        int m0 = mt * 128;
        int n0 = nb * 128;

        if (tid < 128) {
            int m = m0 + tid;
            s_pair[tid] = (m < cnt) ? g_list[e * BATCH + m] : -1;
            s_bias[tid] = benc[(size_t)e * KD + n0 + tid];
        }
        __syncthreads();

        float acc[2][8][4];
#pragma unroll
        for (int i = 0; i < 2; i++)
#pragma unroll
            for (int j = 0; j < 8; j++)
#pragma unroll
                for (int q = 0; q < 4; q++) acc[i][j][q] = 0.f;

        int pairL = s_pair[lrow];
        int tokenL = (pairL >= 0 ? pairL : 0) >> 1;
        const float* xrow = g_X + (size_t)tokenL * DIM + lh;
        const float* wrow = Wenc + (size_t)e * KD * DIM + (size_t)(n0 + lrow) * DIM + lh;

        // chunk 0 -> buf 0
        {
            float4 x0 = *(const float4*)(xrow);
            float4 x1 = *(const float4*)(xrow + 4);
            float4 w0 = *(const float4*)(wrow);
            float4 w1 = *(const float4*)(wrow + 4);
            *(float4*)&Xs[0][lrow * SROW + lh]     = x0;
            *(float4*)&Xs[0][lrow * SROW + lh + 4] = x1;
            *(float4*)&Ws[0][lrow * SROW + lh]     = w0;
            *(float4*)&Ws[0][lrow * SROW + lh + 4] = w1;
        }
        __syncthreads();

#pragma unroll 1
        for (int c = 0; c < NCH; c++) {
            int buf = c & 1;
            float4 px0, px1, pw0, pw1;
            if (c + 1 < NCH) {
                px0 = *(const float4*)(xrow + (c + 1) * CK);
                px1 = *(const float4*)(xrow + (c + 1) * CK + 4);
                pw0 = *(const float4*)(wrow + (c + 1) * CK);
                pw1 = *(const float4*)(wrow + (c + 1) * CK + 4);
            }
            // compute 2 k-steps of 8
#pragma unroll
            for (int ks = 0; ks < 2; ks++) {
                int k0 = ks * 8;
                // A fragments: hi/lo for 2 m-tiles
                uint32_t ahi[2][4], alo[2][4];
#pragma unroll
                for (int mi = 0; mi < 2; mi++) {
                    int r0 = (mbase + mi * 16 + g) * SROW + k0 + t;
                    int r1 = (mbase + mi * 16 + g + 8) * SROW + k0 + t;
                    float a0 = Xs[buf][r0];
                    float a1 = Xs[buf][r1];
                    float a2 = Xs[buf][r0 + 4];
                    float a3 = Xs[buf][r1 + 4];
                    ahi[mi][0] = f2tf(a0); alo[mi][0] = f2tf(a0 - __uint_as_float(ahi[mi][0]));
                    ahi[mi][1] = f2tf(a1); alo[mi][1] = f2tf(a1 - __uint_as_float(ahi[mi][1]));
                    ahi[mi][2] = f2tf(a2); alo[mi][2] = f2tf(a2 - __uint_as_float(ahi[mi][2]));
                    ahi[mi][3] = f2tf(a3); alo[mi][3] = f2tf(a3 - __uint_as_float(ahi[mi][3]));
                }
#pragma unroll
                for (int nt = 0; nt < 8; nt++) {
                    int rb = (nbase + nt * 8 + g) * SROW + k0 + t;
                    float b0 = Ws[buf][rb];
                    float b1 = Ws[buf][rb + 4];
                    uint32_t bhi[2], blo[2];
                    bhi[0] = f2tf(b0); blo[0] = f2tf(b0 - __uint_as_float(bhi[0]));
                    bhi[1] = f2tf(b1); blo[1] = f2tf(b1 - __uint_as_float(bhi[1]));
#pragma unroll
                    for (int mi = 0; mi < 2; mi++) {
                        mma_tf32(acc[mi][nt], ahi[mi], bhi);
                        mma_tf32(acc[mi][nt], ahi[mi], blo);
                        mma_tf32(acc[mi][nt], alo[mi], bhi);
                    }
                }
            }
            if (c + 1 < NCH) {
                int nb2 = buf ^ 1;
                *(float4*)&Xs[nb2][lrow * SROW + lh]     = px0;
                *(float4*)&Xs[nb2][lrow * SROW + lh + 4] = px1;
                *(float4*)&Ws[nb2][lrow * SROW + lh]     = pw0;
                *(float4*)&Ws[nb2][lrow * SROW + lh + 4] = pw1;
                __syncthreads();
            }
        }

        // epilogue: bias + relu + gate-weight
#pragma unroll
        for (int mi = 0; mi < 2; mi++) {
#pragma unroll
            for (int half = 0; half < 2; half++) {
                int m = mbase + mi * 16 + g + half * 8;
                int pair = s_pair[m];
                if (pair < 0) continue;
                float wgt = g_w[pair];
                float* dst = g_F + (size_t)pair * KD + n0;
#pragma unroll
                for (int nt = 0; nt < 8; nt++) {
                    int col = nbase + nt * 8 + 2 * t;
                    float2 o;
                    o.x = fmaxf(acc[mi][nt][half * 2 + 0] + s_bias[col],     0.f) * wgt;
                    o.y = fmaxf(acc[mi][nt][half * 2 + 1] + s_bias[col + 1], 0.f) * wgt;
                    *(float2*)(dst + col) = o;
                }
            }
        }
        __syncthreads();   // s_pair/s_bias reads done before next tile overwrites
    }
}

// ---------------- decode: hist + 2-bit radix top-50 ----------------
__global__ void __launch_bounds__(192) k_decode(const float* __restrict__ b_dec,
                                                const float* __restrict__ Wdec,
                                                float* __restrict__ out) {
    int b = blockIdx.x;
    int tid = threadIdx.x;
    int lane = tid & 31;
    int wid = tid >> 5;

    __shared__ float    sf[KD];
    __shared__ int      hist[256];
    __shared__ int      cntS[36];
    __shared__ int      sel[56];
    __shared__ int      s_nsel, s_E, s_special;

    float4 bd = *(const float4*)(b_dec + tid * 4);
    u64 acc01, acc23;
    PACK2(acc01, bd.x, bd.y);
    PACK2(acc23, bd.z, bd.w);

    for (int slot = 0; slot < 2; slot++) {
        int pair = b * 2 + slot;
        int e = g_route[pair];
        const float* Fr = g_F + (size_t)pair * KD;

        for (int i = tid; i < 256; i += 192) hist[i] = 0;
        if (tid < 36) cntS[tid] = 0;
        unsigned rv[8];
#pragma unroll
        for (int j = 0; j < 8; j++) {
            float v = Fr[tid + 192 * j];
            sf[tid + 192 * j] = v;
            rv[j] = __float_as_uint(v);
        }
        __syncthreads();

#pragma unroll
        for (int j = 0; j < 8; j++)
            if (rv[j]) atomicAdd(&hist[rv[j] >> 23], 1);
        __syncthreads();

        if (wid == 0) {
            int base = 255 - 8 * lane;
            int c[8], cl = 0;
#pragma unroll
            for (int j = 0; j < 8; j++) { c[j] = hist[base - j]; cl += c[j]; }
            int incl = cl;
#pragma unroll
            for (int o = 1; o < 32; o <<= 1) {
                int tt = __shfl_up_sync(0xffffffffu, incl, o);
                if (lane >= o) incl += tt;
            }
            int pre = incl - cl;
            int total = __shfl_sync(0xffffffffu, incl, 31);
            if (total < KSEL) {
                if (lane == 0) s_special = 1;
            } else {
                bool owns = (pre < KSEL) && (incl >= KSEL);
                unsigned om = __ballot_sync(0xffffffffu, owns);
                int ol = __ffs(om) - 1;
                int Ev = 0;
                if (owns) {
                    int cum = pre;
#pragma unroll
                    for (int j = 0; j < 8; j++) {
                        if (cum + c[j] >= KSEL) { Ev = base - j; break; }
                        cum += c[j];
                    }
                }
                Ev = __shfl_sync(0xffffffffu, Ev, ol);
                if (lane == 0) { s_special = 0; s_E = Ev; }
            }
        }
        __syncthreads();

        unsigned thr;
        if (!s_special) {
            unsigned lo = (unsigned)s_E << 23;
#pragma unroll 1
            for (int it = 0; it < 11; it++) {
                int s = 21 - 2 * it;
                unsigned t1 = lo | (1u << s);
                unsigned t2 = lo | (2u << s);
                unsigned t3 = lo | (3u << s);
                int c1 = 0, c2 = 0, c3 = 0;
#pragma unroll
                for (int j = 0; j < 8; j++) {
                    c1 += (rv[j] >= t1);
                    c2 += (rv[j] >= t2);
                    c3 += (rv[j] >= t3);
                }
                c1 = __reduce_add_sync(0xffffffffu, c1);
                c2 = __reduce_add_sync(0xffffffffu, c2);
                c3 = __reduce_add_sync(0xffffffffu, c3);
                if (lane == 0) {
                    atomicAdd(&cntS[it * 3 + 0], c1);
                    atomicAdd(&cntS[it * 3 + 1], c2);
                    atomicAdd(&cntS[it * 3 + 2], c3);
                }
                __syncthreads();
                int C1 = cntS[it * 3 + 0], C2 = cntS[it * 3 + 1], C3 = cntS[it * 3 + 2];
                unsigned d = (C3 >= KSEL) ? 3u : (C2 >= KSEL) ? 2u : (C1 >= KSEL) ? 1u : 0u;
                lo |= d << s;
            }
            {
                unsigned tt = lo | 1u;
                int c = 0;
#pragma unroll
                for (int j = 0; j < 8; j++) c += (rv[j] >= tt);
                c = __reduce_add_sync(0xffffffffu, c);
                if (lane == 0) atomicAdd(&cntS[33], c);
                __syncthreads();
                if (cntS[33] >= KSEL) lo |= 1u;
            }
            thr = lo;
        } else {
            thr = 1u;
        }

        if (tid < 32) {
            int ns = 0;
            for (int base = 0; base < KD; base += 32) {
                unsigned bits = __float_as_uint(sf[base + tid]);
                bool p = (bits >= thr) && (bits != 0u);
                unsigned msk = __ballot_sync(0xffffffffu, p);
                int pos = ns + __popc(msk & ((1u << tid) - 1u));
                if (p && pos < KSEL) sel[pos] = base + tid;
                ns += __popc(msk);
            }
            if (tid == 0) s_nsel = (ns < KSEL ? ns : KSEL);
        }
        __syncthreads();
        int nsel = s_nsel;

        const float* Wd = Wdec + (size_t)e * KD * DIM + tid * 4;
        int i = 0;
        for (; i + 4 <= nsel; i += 4) {
            int k0 = sel[i], k1 = sel[i + 1], k2 = sel[i + 2], k3 = sel[i + 3];
            float f0 = sf[k0], f1 = sf[k1], f2 = sf[k2], f3 = sf[k3];
            float4 w0 = *(const float4*)(Wd + (size_t)k0 * DIM);
            float4 w1 = *(const float4*)(Wd + (size_t)k1 * DIM);
            float4 w2 = *(const float4*)(Wd + (size_t)k2 * DIM);
            float4 w3 = *(const float4*)(Wd + (size_t)k3 * DIM);
            u64 fp, t;
            PACK2(fp, f0, f0);
            PACK2(t, w0.x, w0.y); FMA2(acc01, fp, t);
            PACK2(t, w0.z, w0.w); FMA2(acc23, fp, t);
            PACK2(fp, f1, f1);
            PACK2(t, w1.x, w1.y); FMA2(acc01, fp, t);
            PACK2(t, w1.z, w1.w); FMA2(acc23, fp, t);
            PACK2(fp, f2, f2);
            PACK2(t, w2.x, w2.y); FMA2(acc01, fp, t);
            PACK2(t, w2.z, w2.w); FMA2(acc23, fp, t);
            PACK2(fp, f3, f3);
            PACK2(t, w3.x, w3.y); FMA2(acc01, fp, t);
            PACK2(t, w3.z, w3.w); FMA2(acc23, fp, t);
        }
        for (; i < nsel; i++) {
            int k0 = sel[i];
            float f0 = sf[k0];
            float4 w0 = *(const float4*)(Wd + (size_t)k0 * DIM);
            u64 fp, t;
            PACK2(fp, f0, f0);
            PACK2(t, w0.x, w0.y); FMA2(acc01, fp, t);
            PACK2(t, w0.z, w0.w); FMA2(acc23, fp, t);
        }
        __syncthreads();
    }

    float4 r;
    UNPACK2(r.x, r.y, acc01);
    UNPACK2(r.z, r.w, acc23);
    *(float4*)(out + (size_t)b * DIM + tid * 4) = r;
}

// ---------------- launch ----------------
extern "C" void kernel_launch(void* const* d_in, const int* in_sizes, int n_in,
                              void* d_out, int out_size) {
    const float* x      = (const float*)d_in[0];
    const float* Wg     = (const float*)d_in[1];
    const float* bg     = (const float*)d_in[2];
    const float* b_gate = (const float*)d_in[3];
    const float* b_dec  = (const float*)d_in[4];
    const float* Wenc   = (const float*)d_in[5];
    const float* benc   = (const float*)d_in[6];
    const float* Wdec   = (const float*)d_in[7];
    float* out = (float*)d_out;

    k_init<<<1, 32>>>();
    k_gate<<<BATCH / 4, 128>>>(x, Wg, bg, b_gate, b_dec);
    k_encode<<<296, 256>>>(Wenc, benc);
    k_decode<<<BATCH, 192>>>(b_dec, Wdec, out);
}